// round 6
// baseline (speedup 1.0000x reference)
#include <cuda_runtime.h>
#include <cuda_bf16.h>

#define WARPS_PER_BLOCK 8
#define NTHREADS (WARPS_PER_BLOCK * 32)
#define NDIR_MAX 800
#define NQUAD_MAIN 192            // 6 * 32 full-warp quad iterations

__device__ __forceinline__ float fex2(float x){ float r; asm("ex2.approx.f32 %0,%1;" : "=f"(r) : "f"(x)); return r; }
__device__ __forceinline__ float flg2(float x){ float r; asm("lg2.approx.f32 %0,%1;" : "=f"(r) : "f"(x)); return r; }
__device__ __forceinline__ float frcp(float x){ float r; asm("rcp.approx.f32 %0,%1;" : "=f"(r) : "f"(x)); return r; }

__global__ __launch_bounds__(NTHREADS)
void closure_kernel(const float* __restrict__ F4,
                    const float* __restrict__ gdx,
                    const float* __restrict__ gdy,
                    const float* __restrict__ gdz,
                    const float* __restrict__ gqw,
                    float* __restrict__ out,
                    int B, int nd)
{
    // Quadrature symmetry (21x41 midpoint grid, nd==800 => 20 theta x 40 phi):
    //  - antipode of (ti,pj) is (19-ti, pj+20), equal weight
    //  - theta reflection (19-ti, pj) flips z only, equal weight
    // => quads over ti in 0..9, pj in 0..19: members (x,y,z),(x,y,-z),(-x,-y,z),(-x,-y,-z)
    __shared__ float4 s_dir[NDIR_MAX];     // quads (x,y,z,log2 w) for paired; raw dirs otherwise
    __shared__ float4 s_single[32];        // leftover 8 quads expanded to 32 single dirs
    __shared__ float  wred[WARPS_PER_BLOCK][24 * 33];
    const bool paired = (nd == 800);
    if (paired) {
        for (int j = threadIdx.x; j < NQUAD_MAIN; j += NTHREADS) {
            int ti = j / 20, pj = j % 20;
            int d = ti * 40 + pj;
            s_dir[j] = make_float4(gdx[d], gdy[d], gdz[d], flg2(gqw[d]));
        }
        for (int j = threadIdx.x; j < 32; j += NTHREADS) {
            int qq = NQUAD_MAIN + (j >> 2);     // 192..199 -> ti=9, pj=12..19
            int m  = j & 3;
            int ti = qq / 20, pj = qq % 20;
            int ii = (m & 1) ? (19 - ti) : ti;
            int jj = (m & 2) ? (pj + 20)  : pj;
            int d = ii * 40 + jj;
            s_single[j] = make_float4(gdx[d], gdy[d], gdz[d], flg2(gqw[d]));
        }
    } else {
        for (int j = threadIdx.x; j < nd; j += NTHREADS)
            s_dir[j] = make_float4(gdx[j], gdy[j], gdz[j], flg2(gqw[j]));
    }
    __syncthreads();

    const int warp = threadIdx.x >> 5;
    const int lane = threadIdx.x & 31;
    const int b = blockIdx.x * WARPS_PER_BLOCK + warp;
    if (b >= B) return;

    const float EPS    = 1e-12f;
    const float INV4PI = 0.07957747154594767f;
    const float LOG2E  = 1.4426950408889634f;

    // vectorized input load: 24 floats = 6 float4
    const float4* in4 = (const float4*)(F4 + (size_t)b * 24);
    float4 i0 = in4[0], i1 = in4[1], i2 = in4[2], i3 = in4[3], i4 = in4[4], i5 = in4[5];

    // species: 0=e, 1=ebar, 2=x, 3=xbar
    float Fx[4], Fy[4], Fz[4], Ns[4];
    Fx[0] = i0.x;  Fy[0] = i0.y;  Fz[0] = i0.z;  Ns[0] = i0.w;
    Fx[1] = i3.x;  Fy[1] = i3.y;  Fz[1] = i3.z;  Ns[1] = i3.w;
    Fx[2] = 0.5f*(i1.x + i2.x); Fy[2] = 0.5f*(i1.y + i2.y);
    Fz[2] = 0.5f*(i1.z + i2.z); Ns[2] = 0.5f*(i1.w + i2.w);
    Fx[3] = 0.5f*(i4.x + i5.x); Fy[3] = 0.5f*(i4.y + i5.y);
    Fz[3] = 0.5f*(i4.z + i5.z); Ns[3] = 0.5f*(i4.w + i5.w);

    float La[4], Kx[4], Ky[4], Kz[4];
    #pragma unroll
    for (int s = 0; s < 4; s++) {
        float N   = fmaxf(Ns[s], EPS);
        float ss  = Fx[s]*Fx[s] + Fy[s]*Fy[s] + Fz[s]*Fz[s];
        float rs  = rsqrtf(fmaxf(ss, 1e-30f));   // 1/nrm
        float nrm = ss * rs;
        float f   = fminf(fmaxf(nrm * frcp(N), 0.0f), 0.999999f);
        float f2 = f*f, f4 = f2*f2, f6 = f4*f2, f8 = f4*f4;
        float denom = 3.0f - 1.00651f*f2 - 0.962251f*f4 + 1.47353f*f6 - 0.48953f*f8;
        float p = 1.0f - 2.0f*(1.0f - f)*(1.0f + 1.01524f*f) * frcp(fmaxf(denom, EPS));
        float Z = 2.0f*f * frcp(fmaxf(1.0f - p, 1e-6f));
        Z = fminf(Z, 85.0f);
        float zsz;
        if (fabsf(Z) < 1e-4f) {
            float z2 = Z*Z;
            zsz = 1.0f - z2*(1.0f/6.0f) + z2*z2*(1.0f/120.0f);
        } else {
            float E  = fex2(Z * LOG2E);
            float Em = fex2(-Z * LOG2E);
            zsz = Z * frcp(0.5f * (E - Em));
        }
        float A = N * INV4PI * zsz;              // A > 0
        La[s] = flg2(A);
        float scl = Z * LOG2E * rs;
        Kx[s] = Fx[s]*scl; Ky[s] = Fy[s]*scl; Kz[s] = Fz[s]*scl;
    }

    // acc[4s+k]: totals of (w*g_s)*{1,dx,dy,dz};
    // acc[16+k]: sum over {delta>=0} of w*u*{...}; acc[20+k]: same for w*v
    float acc[24];
    #pragma unroll
    for (int i = 0; i < 24; i++) acc[i] = 0.0f;

    if (paired) {
        #pragma unroll 2
        for (int q = lane; q < NQUAD_MAIN; q += 32) {
            float4 t4 = s_dir[q];
            float qx = t4.x, qy = t4.y, qz = t4.z, lw = t4.w;
            float Mh[4], Cz[4], gp[4], gm[4];
            // half 1: members (x,y,z) and (x,y,-z)
            #pragma unroll
            for (int s = 0; s < 4; s++) {
                float a  = fmaf(Ky[s], qy, Kx[s]*qx);
                float cz = Kz[s]*qz;
                float c0 = La[s] + lw;
                float P = c0 + a;
                Mh[s] = c0 - a;
                Cz[s] = cz;
                gp[s] = fex2(P + cz);
                gm[s] = fex2(P - cz);
                float sm = gp[s] + gm[s];
                float df = gp[s] - gm[s];
                acc[4*s+0] += sm;
                acc[4*s+1] = fmaf(sm, qx, acc[4*s+1]);
                acc[4*s+2] = fmaf(sm, qy, acc[4*s+2]);
                acc[4*s+3] = fmaf(df, qz, acc[4*s+3]);
            }
            {   // bucket member (x,y,z)
                float u = gp[0] - gp[2], v = gp[1] - gp[3];
                if (u >= v) {
                    acc[16] += u; acc[17] = fmaf(u, qx, acc[17]); acc[18] = fmaf(u, qy, acc[18]); acc[19] = fmaf(u, qz, acc[19]);
                    acc[20] += v; acc[21] = fmaf(v, qx, acc[21]); acc[22] = fmaf(v, qy, acc[22]); acc[23] = fmaf(v, qz, acc[23]);
                }
            }
            {   // bucket member (x,y,-z)
                float u = gm[0] - gm[2], v = gm[1] - gm[3];
                if (u >= v) {
                    acc[16] += u; acc[17] = fmaf(u, qx, acc[17]); acc[18] = fmaf(u, qy, acc[18]); acc[19] = fmaf(u, -qz, acc[19]);
                    acc[20] += v; acc[21] = fmaf(v, qx, acc[21]); acc[22] = fmaf(v, qy, acc[22]); acc[23] = fmaf(v, -qz, acc[23]);
                }
            }
            // half 2: members (-x,-y,z) and (-x,-y,-z)
            #pragma unroll
            for (int s = 0; s < 4; s++) {
                gp[s] = fex2(Mh[s] + Cz[s]);
                gm[s] = fex2(Mh[s] - Cz[s]);
                float sm = gp[s] + gm[s];
                float df = gp[s] - gm[s];
                acc[4*s+0] += sm;
                acc[4*s+1] = fmaf(sm, -qx, acc[4*s+1]);
                acc[4*s+2] = fmaf(sm, -qy, acc[4*s+2]);
                acc[4*s+3] = fmaf(df, qz, acc[4*s+3]);
            }
            {   // bucket member (-x,-y,z)
                float u = gp[0] - gp[2], v = gp[1] - gp[3];
                if (u >= v) {
                    acc[16] += u; acc[17] = fmaf(u, -qx, acc[17]); acc[18] = fmaf(u, -qy, acc[18]); acc[19] = fmaf(u, qz, acc[19]);
                    acc[20] += v; acc[21] = fmaf(v, -qx, acc[21]); acc[22] = fmaf(v, -qy, acc[22]); acc[23] = fmaf(v, qz, acc[23]);
                }
            }
            {   // bucket member (-x,-y,-z)
                float u = gm[0] - gm[2], v = gm[1] - gm[3];
                if (u >= v) {
                    acc[16] += u; acc[17] = fmaf(u, -qx, acc[17]); acc[18] = fmaf(u, -qy, acc[18]); acc[19] = fmaf(u, -qz, acc[19]);
                    acc[20] += v; acc[21] = fmaf(v, -qx, acc[21]); acc[22] = fmaf(v, -qy, acc[22]); acc[23] = fmaf(v, -qz, acc[23]);
                }
            }
        }
        // leftover 32 single directions, one per lane
        {
            float4 t4 = s_single[lane];
            float qx = t4.x, qy = t4.y, qz = t4.z, lw = t4.w;
            float g[4];
            #pragma unroll
            for (int s = 0; s < 4; s++) {
                float t = fmaf(Kx[s], qx, fmaf(Ky[s], qy, Kz[s]*qz));
                g[s] = fex2(t + La[s] + lw);
                acc[4*s+0] += g[s];
                acc[4*s+1] = fmaf(g[s], qx, acc[4*s+1]);
                acc[4*s+2] = fmaf(g[s], qy, acc[4*s+2]);
                acc[4*s+3] = fmaf(g[s], qz, acc[4*s+3]);
            }
            float u = g[0] - g[2], v = g[1] - g[3];
            if (u >= v) {
                acc[16] += u; acc[17] = fmaf(u, qx, acc[17]); acc[18] = fmaf(u, qy, acc[18]); acc[19] = fmaf(u, qz, acc[19]);
                acc[20] += v; acc[21] = fmaf(v, qx, acc[21]); acc[22] = fmaf(v, qy, acc[22]); acc[23] = fmaf(v, qz, acc[23]);
            }
        }
    } else {
        for (int d = lane; d < nd; d += 32) {
            float4 q = s_dir[d];
            float lw = q.w;
            float g[4];
            #pragma unroll
            for (int s = 0; s < 4; s++) {
                float t = fmaf(Kx[s], q.x, fmaf(Ky[s], q.y, Kz[s]*q.z));
                g[s] = fex2(t + La[s] + lw);
                acc[4*s+0] += g[s];
                acc[4*s+1] = fmaf(g[s], q.x, acc[4*s+1]);
                acc[4*s+2] = fmaf(g[s], q.y, acc[4*s+2]);
                acc[4*s+3] = fmaf(g[s], q.z, acc[4*s+3]);
            }
            float wu = g[0] - g[2], wv = g[1] - g[3];
            if (wu >= wv) {
                acc[16] += wu; acc[17] = fmaf(wu, q.x, acc[17]); acc[18] = fmaf(wu, q.y, acc[18]); acc[19] = fmaf(wu, q.z, acc[19]);
                acc[20] += wv; acc[21] = fmaf(wv, q.x, acc[21]); acc[22] = fmaf(wv, q.y, acc[22]); acc[23] = fmaf(wv, q.z, acc[23]);
            }
        }
    }

    // single-pass warp reduction via SMEM transpose, then shfl broadcast
    float* wr = wred[warp];
    #pragma unroll
    for (int i = 0; i < 24; i++) wr[i*33 + lane] = acc[i];
    __syncwarp();
    float tot = 0.0f;
    if (lane < 24) {
        float p0 = 0.f, p1 = 0.f, p2 = 0.f, p3 = 0.f;
        const float* row = wr + lane*33;
        #pragma unroll
        for (int j = 0; j < 32; j += 4) { p0 += row[j]; p1 += row[j+1]; p2 += row[j+2]; p3 += row[j+3]; }
        tot = (p0 + p1) + (p2 + p3);
    }
    float r[24];
    #pragma unroll
    for (int k = 0; k < 24; k++) r[k] = __shfl_sync(0xffffffffu, tot, k);

    float Su[4], Sv[4];
    #pragma unroll
    for (int k = 0; k < 4; k++) {
        Su[k] = r[0 + k] - r[8 + k];   // total sum w*u*{1,x,y,z}
        Sv[k] = r[4 + k] - r[12 + k];  // total sum w*v*{1,x,y,z}
    }
    float Iplus  = r[16] - r[20];
    float Iminus = (Sv[0] - r[20]) - (Su[0] - r[16]);
    float Ips = fmaxf(Iplus,  EPS);
    float Ims = fmaxf(Iminus, EPS);
    float cp, cn;
    if (Iplus < Iminus) {
        cp = 1.0f / 3.0f;
        cn = fminf(fmaxf(1.0f - (2.0f/3.0f)*(Ips/Ims), 0.0f), 1.0f);
    } else {
        cn = 1.0f / 3.0f;
        cp = fminf(fmaxf(1.0f - (2.0f/3.0f)*(Ims/Ips), 0.0f), 1.0f);
    }
    float growth = sqrtf(fmaxf(Iplus * Iminus, 0.0f));

    float n0[4], n1[4], n2[4], n3[4];
    #pragma unroll
    for (int k = 0; k < 4; k++) {
        float Pu = cp*r[16 + k] + cn*(Su[k] - r[16 + k]);  // sum w*Psur*u
        float Pv = cp*r[20 + k] + cn*(Sv[k] - r[20 + k]);  // sum w*Psur*v
        n0[k] = r[8 + k]  + Pu;                            // e
        n1[k] = r[12 + k] + Pv;                            // ebar
        n2[k] = 0.5f*(r[0 + k] + r[8 + k])  - 0.5f*Pu;     // x
        n3[k] = 0.5f*(r[4 + k] + r[12 + k]) - 0.5f*Pv;     // xbar
    }

    // F4mix layout (B,2,3,4): channel order [Fx,Fy,Fz,N]
    float4* ob = (float4*)(out + (size_t)b * 24);
    if (lane == 0) ob[0] = make_float4(n0[1], n0[2], n0[3], n0[0]); // i=0,f=0 (e)
    if (lane == 1) ob[1] = make_float4(n2[1], n2[2], n2[3], n2[0]); // i=0,f=1 (x)
    if (lane == 2) ob[2] = make_float4(n2[1], n2[2], n2[3], n2[0]); // i=0,f=2 (x)
    if (lane == 3) ob[3] = make_float4(n1[1], n1[2], n1[3], n1[0]); // i=1,f=0 (ebar)
    if (lane == 4) ob[4] = make_float4(n3[1], n3[2], n3[3], n3[0]); // i=1,f=1 (xbar)
    if (lane == 5) ob[5] = make_float4(n3[1], n3[2], n3[3], n3[0]); // i=1,f=2 (xbar)
    if (lane == 6) out[(size_t)B * 24 + b] = growth;
}

extern "C" void kernel_launch(void* const* d_in, const int* in_sizes, int n_in,
                              void* d_out, int out_size) {
    const float* F4  = (const float*)d_in[0];
    const float* ddx = (const float*)d_in[1];
    const float* ddy = (const float*)d_in[2];
    const float* ddz = (const float*)d_in[3];
    const float* dqw = (const float*)d_in[4];
    float* out = (float*)d_out;

    int B  = in_sizes[0] / 24;
    int nd = in_sizes[1];

    int grid = (B + WARPS_PER_BLOCK - 1) / WARPS_PER_BLOCK;
    closure_kernel<<<grid, NTHREADS>>>(F4, ddx, ddy, ddz, dqw, out, B, nd);
}

// round 7
// speedup vs baseline: 1.5421x; 1.5421x over previous
#include <cuda_runtime.h>
#include <cuda_bf16.h>

#define WARPS_PER_BLOCK 8
#define NTHREADS (WARPS_PER_BLOCK * 32)
#define NDIR_MAX 800

__device__ __forceinline__ float fex2(float x){ float r; asm("ex2.approx.f32 %0,%1;" : "=f"(r) : "f"(x)); return r; }
__device__ __forceinline__ float flg2(float x){ float r; asm("lg2.approx.f32 %0,%1;" : "=f"(r) : "f"(x)); return r; }
__device__ __forceinline__ float frcp(float x){ float r; asm("rcp.approx.f32 %0,%1;" : "=f"(r) : "f"(x)); return r; }

__global__ __launch_bounds__(NTHREADS, 4)
void closure_kernel(const float* __restrict__ F4,
                    const float* __restrict__ gdx,
                    const float* __restrict__ gdy,
                    const float* __restrict__ gdz,
                    const float* __restrict__ gqw,
                    float* __restrict__ out,
                    int B, int nd)
{
    // paired path: dirs 0..399 have exact antipodes 400..799 with equal weight
    __shared__ float4 s_dir[NDIR_MAX];               // (dx,dy,dz, log2(w))
    __shared__ float  wred[WARPS_PER_BLOCK][24 * 33];
    const bool paired = (nd == 800);
    const int ntab = paired ? 400 : nd;
    for (int j = threadIdx.x; j < ntab; j += NTHREADS)
        s_dir[j] = make_float4(gdx[j], gdy[j], gdz[j], flg2(gqw[j]));
    __syncthreads();

    const int warp = threadIdx.x >> 5;
    const int lane = threadIdx.x & 31;
    const int b = blockIdx.x * WARPS_PER_BLOCK + warp;
    if (b >= B) return;

    const float EPS    = 1e-12f;
    const float INV4PI = 0.07957747154594767f;
    const float LOG2E  = 1.4426950408889634f;

    // vectorized input load: 24 floats = 6 float4
    const float4* in4 = (const float4*)(F4 + (size_t)b * 24);
    float4 i0 = in4[0], i1 = in4[1], i2 = in4[2], i3 = in4[3], i4 = in4[4], i5 = in4[5];

    // species: 0=e, 1=ebar, 2=x, 3=xbar
    float Fx[4], Fy[4], Fz[4], Ns[4];
    Fx[0] = i0.x;  Fy[0] = i0.y;  Fz[0] = i0.z;  Ns[0] = i0.w;
    Fx[1] = i3.x;  Fy[1] = i3.y;  Fz[1] = i3.z;  Ns[1] = i3.w;
    Fx[2] = 0.5f*(i1.x + i2.x); Fy[2] = 0.5f*(i1.y + i2.y);
    Fz[2] = 0.5f*(i1.z + i2.z); Ns[2] = 0.5f*(i1.w + i2.w);
    Fx[3] = 0.5f*(i4.x + i5.x); Fy[3] = 0.5f*(i4.y + i5.y);
    Fz[3] = 0.5f*(i4.z + i5.z); Ns[3] = 0.5f*(i4.w + i5.w);

    float La[4], Kx[4], Ky[4], Kz[4];
    #pragma unroll
    for (int s = 0; s < 4; s++) {
        float N   = fmaxf(Ns[s], EPS);
        float ss  = Fx[s]*Fx[s] + Fy[s]*Fy[s] + Fz[s]*Fz[s];
        float rs  = rsqrtf(fmaxf(ss, 1e-30f));   // 1/nrm
        float nrm = ss * rs;
        float f   = fminf(fmaxf(nrm * frcp(N), 0.0f), 0.999999f);
        float f2 = f*f, f4 = f2*f2, f6 = f4*f2, f8 = f4*f4;
        float denom = 3.0f - 1.00651f*f2 - 0.962251f*f4 + 1.47353f*f6 - 0.48953f*f8;
        float p = 1.0f - 2.0f*(1.0f - f)*(1.0f + 1.01524f*f) * frcp(fmaxf(denom, EPS));
        float Z = 2.0f*f * frcp(fmaxf(1.0f - p, 1e-6f));
        Z = fminf(Z, 85.0f);
        float zsz;
        if (fabsf(Z) < 1e-4f) {
            float z2 = Z*Z;
            zsz = 1.0f - z2*(1.0f/6.0f) + z2*z2*(1.0f/120.0f);
        } else {
            float E  = fex2(Z * LOG2E);
            float Em = fex2(-Z * LOG2E);
            zsz = Z * frcp(0.5f * (E - Em));
        }
        float A = N * INV4PI * zsz;              // A > 0
        La[s] = flg2(A);
        float scl = Z * LOG2E * rs;
        Kx[s] = Fx[s]*scl; Ky[s] = Fy[s]*scl; Kz[s] = Fz[s]*scl;
    }

    // acc[4s+k]: totals of (w*g_s)*{1,dx,dy,dz};
    // acc[16+k]: sum over {delta>=0} of w*u*{...}; acc[20+k]: same for w*v
    float acc[24];
    #pragma unroll
    for (int i = 0; i < 24; i++) acc[i] = 0.0f;

    if (paired) {
        #pragma unroll 4
        for (int pr = lane; pr < 400; pr += 32) {
            float4 q = s_dir[pr];
            float lw = q.w;
            float gp[4], gm[4];
            #pragma unroll
            for (int s = 0; s < 4; s++) {
                float t = fmaf(Kx[s], q.x, fmaf(Ky[s], q.y, Kz[s]*q.z));
                float c = La[s] + lw;            // fold weight into exponent
                gp[s] = fex2(c + t);             // w*g at +d
                gm[s] = fex2(c - t);             // w*g at -d
                float sm = gp[s] + gm[s];
                float df = gp[s] - gm[s];
                acc[4*s+0] += sm;
                acc[4*s+1] = fmaf(df, q.x, acc[4*s+1]);
                acc[4*s+2] = fmaf(df, q.y, acc[4*s+2]);
                acc[4*s+3] = fmaf(df, q.z, acc[4*s+3]);
            }
            // positive-delta buckets, +d member
            float up = gp[0] - gp[2], vp = gp[1] - gp[3];
            if (up >= vp) {
                acc[16] += up; acc[17] = fmaf(up, q.x, acc[17]); acc[18] = fmaf(up, q.y, acc[18]); acc[19] = fmaf(up, q.z, acc[19]);
                acc[20] += vp; acc[21] = fmaf(vp, q.x, acc[21]); acc[22] = fmaf(vp, q.y, acc[22]); acc[23] = fmaf(vp, q.z, acc[23]);
            }
            // -d member (moments with negated direction)
            float um = gm[0] - gm[2], vm = gm[1] - gm[3];
            if (um >= vm) {
                acc[16] += um; acc[17] = fmaf(um, -q.x, acc[17]); acc[18] = fmaf(um, -q.y, acc[18]); acc[19] = fmaf(um, -q.z, acc[19]);
                acc[20] += vm; acc[21] = fmaf(vm, -q.x, acc[21]); acc[22] = fmaf(vm, -q.y, acc[22]); acc[23] = fmaf(vm, -q.z, acc[23]);
            }
        }
    } else {
        for (int d = lane; d < nd; d += 32) {
            float4 q = s_dir[d];
            float lw = q.w;
            float g[4];
            #pragma unroll
            for (int s = 0; s < 4; s++) {
                float t = fmaf(Kx[s], q.x, fmaf(Ky[s], q.y, Kz[s]*q.z));
                g[s] = fex2(t + La[s] + lw);
                acc[4*s+0] += g[s];
                acc[4*s+1] = fmaf(g[s], q.x, acc[4*s+1]);
                acc[4*s+2] = fmaf(g[s], q.y, acc[4*s+2]);
                acc[4*s+3] = fmaf(g[s], q.z, acc[4*s+3]);
            }
            float wu = g[0] - g[2], wv = g[1] - g[3];
            if (wu >= wv) {
                acc[16] += wu; acc[17] = fmaf(wu, q.x, acc[17]); acc[18] = fmaf(wu, q.y, acc[18]); acc[19] = fmaf(wu, q.z, acc[19]);
                acc[20] += wv; acc[21] = fmaf(wv, q.x, acc[21]); acc[22] = fmaf(wv, q.y, acc[22]); acc[23] = fmaf(wv, q.z, acc[23]);
            }
        }
    }

    // single-pass warp reduction via SMEM transpose, then shfl broadcast
    float* wr = wred[warp];
    #pragma unroll
    for (int i = 0; i < 24; i++) wr[i*33 + lane] = acc[i];
    __syncwarp();
    float tot = 0.0f;
    if (lane < 24) {
        float p0 = 0.f, p1 = 0.f, p2 = 0.f, p3 = 0.f;
        const float* row = wr + lane*33;
        #pragma unroll
        for (int j = 0; j < 32; j += 4) { p0 += row[j]; p1 += row[j+1]; p2 += row[j+2]; p3 += row[j+3]; }
        tot = (p0 + p1) + (p2 + p3);
    }
    float r[24];
    #pragma unroll
    for (int k = 0; k < 24; k++) r[k] = __shfl_sync(0xffffffffu, tot, k);

    float Su[4], Sv[4];
    #pragma unroll
    for (int k = 0; k < 4; k++) {
        Su[k] = r[0 + k] - r[8 + k];   // total sum w*u*{1,x,y,z}
        Sv[k] = r[4 + k] - r[12 + k];  // total sum w*v*{1,x,y,z}
    }
    float Iplus  = r[16] - r[20];
    float Iminus = (Sv[0] - r[20]) - (Su[0] - r[16]);
    float Ips = fmaxf(Iplus,  EPS);
    float Ims = fmaxf(Iminus, EPS);
    float cp, cn;
    if (Iplus < Iminus) {
        cp = 1.0f / 3.0f;
        cn = fminf(fmaxf(1.0f - (2.0f/3.0f)*(Ips/Ims), 0.0f), 1.0f);
    } else {
        cn = 1.0f / 3.0f;
        cp = fminf(fmaxf(1.0f - (2.0f/3.0f)*(Ims/Ips), 0.0f), 1.0f);
    }
    float growth = sqrtf(fmaxf(Iplus * Iminus, 0.0f));

    float n0[4], n1[4], n2[4], n3[4];
    #pragma unroll
    for (int k = 0; k < 4; k++) {
        float Pu = cp*r[16 + k] + cn*(Su[k] - r[16 + k]);  // sum w*Psur*u
        float Pv = cp*r[20 + k] + cn*(Sv[k] - r[20 + k]);  // sum w*Psur*v
        n0[k] = r[8 + k]  + Pu;                            // e
        n1[k] = r[12 + k] + Pv;                            // ebar
        n2[k] = 0.5f*(r[0 + k] + r[8 + k])  - 0.5f*Pu;     // x
        n3[k] = 0.5f*(r[4 + k] + r[12 + k]) - 0.5f*Pv;     // xbar
    }

    // F4mix layout (B,2,3,4): channel order [Fx,Fy,Fz,N]
    float4* ob = (float4*)(out + (size_t)b * 24);
    if (lane == 0) ob[0] = make_float4(n0[1], n0[2], n0[3], n0[0]); // i=0,f=0 (e)
    if (lane == 1) ob[1] = make_float4(n2[1], n2[2], n2[3], n2[0]); // i=0,f=1 (x)
    if (lane == 2) ob[2] = make_float4(n2[1], n2[2], n2[3], n2[0]); // i=0,f=2 (x)
    if (lane == 3) ob[3] = make_float4(n1[1], n1[2], n1[3], n1[0]); // i=1,f=0 (ebar)
    if (lane == 4) ob[4] = make_float4(n3[1], n3[2], n3[3], n3[0]); // i=1,f=1 (xbar)
    if (lane == 5) ob[5] = make_float4(n3[1], n3[2], n3[3], n3[0]); // i=1,f=2 (xbar)
    if (lane == 6) out[(size_t)B * 24 + b] = growth;
}

extern "C" void kernel_launch(void* const* d_in, const int* in_sizes, int n_in,
                              void* d_out, int out_size) {
    const float* F4  = (const float*)d_in[0];
    const float* ddx = (const float*)d_in[1];
    const float* ddy = (const float*)d_in[2];
    const float* ddz = (const float*)d_in[3];
    const float* dqw = (const float*)d_in[4];
    float* out = (float*)d_out;

    int B  = in_sizes[0] / 24;
    int nd = in_sizes[1];

    int grid = (B + WARPS_PER_BLOCK - 1) / WARPS_PER_BLOCK;
    closure_kernel<<<grid, NTHREADS>>>(F4, ddx, ddy, ddz, dqw, out, B, nd);
}

// round 8
// speedup vs baseline: 1.8152x; 1.1771x over previous
#include <cuda_runtime.h>
#include <cuda_bf16.h>

#define WARPS_PER_BLOCK 8
#define NTHREADS (WARPS_PER_BLOCK * 32)
#define NDIR_MAX 800

__device__ __forceinline__ float fex2(float x){ float r; asm("ex2.approx.f32 %0,%1;" : "=f"(r) : "f"(x)); return r; }
__device__ __forceinline__ float flg2(float x){ float r; asm("lg2.approx.f32 %0,%1;" : "=f"(r) : "f"(x)); return r; }
__device__ __forceinline__ float frcp(float x){ float r; asm("rcp.approx.f32 %0,%1;" : "=f"(r) : "f"(x)); return r; }

__global__ __launch_bounds__(NTHREADS, 4)
void closure_kernel(const float* __restrict__ F4,
                    const float* __restrict__ gdx,
                    const float* __restrict__ gdy,
                    const float* __restrict__ gdz,
                    const float* __restrict__ gqw,
                    float* __restrict__ out,
                    int B, int nd)
{
    // paired path: dirs 0..399 have exact antipodes 400..799 with equal weight
    __shared__ float4 s_dir[NDIR_MAX];               // (dx,dy,dz, log2(w))
    const bool paired = (nd == 800);
    const int ntab = paired ? 400 : nd;
    for (int j = threadIdx.x; j < ntab; j += NTHREADS)
        s_dir[j] = make_float4(gdx[j], gdy[j], gdz[j], flg2(gqw[j]));
    __syncthreads();

    const int warp = threadIdx.x >> 5;
    const int lane = threadIdx.x & 31;
    const int hl   = lane & 15;                      // lane within half-warp
    // two batches per warp: lanes 0-15 -> b0, lanes 16-31 -> b1
    int b = blockIdx.x * (WARPS_PER_BLOCK * 2) + warp * 2 + (lane >> 4);
    bool active = (b < B);
    int bs = active ? b : 0;                         // safe index for loads

    const float EPS    = 1e-12f;
    const float INV4PI = 0.07957747154594767f;
    const float LOG2E  = 1.4426950408889634f;

    // vectorized input load: 24 floats = 6 float4 (per-half-warp batch)
    const float4* in4 = (const float4*)(F4 + (size_t)bs * 24);
    float4 i0 = in4[0], i1 = in4[1], i2 = in4[2], i3 = in4[3], i4 = in4[4], i5 = in4[5];

    // species: 0=e, 1=ebar, 2=x, 3=xbar
    float Fx[4], Fy[4], Fz[4], Ns[4];
    Fx[0] = i0.x;  Fy[0] = i0.y;  Fz[0] = i0.z;  Ns[0] = i0.w;
    Fx[1] = i3.x;  Fy[1] = i3.y;  Fz[1] = i3.z;  Ns[1] = i3.w;
    Fx[2] = 0.5f*(i1.x + i2.x); Fy[2] = 0.5f*(i1.y + i2.y);
    Fz[2] = 0.5f*(i1.z + i2.z); Ns[2] = 0.5f*(i1.w + i2.w);
    Fx[3] = 0.5f*(i4.x + i5.x); Fy[3] = 0.5f*(i4.y + i5.y);
    Fz[3] = 0.5f*(i4.z + i5.z); Ns[3] = 0.5f*(i4.w + i5.w);

    float La[4], Kx[4], Ky[4], Kz[4];
    #pragma unroll
    for (int s = 0; s < 4; s++) {
        float N   = fmaxf(Ns[s], EPS);
        float ss  = Fx[s]*Fx[s] + Fy[s]*Fy[s] + Fz[s]*Fz[s];
        float rs  = rsqrtf(fmaxf(ss, 1e-30f));   // 1/nrm
        float nrm = ss * rs;
        float f   = fminf(fmaxf(nrm * frcp(N), 0.0f), 0.999999f);
        float f2 = f*f, f4 = f2*f2, f6 = f4*f2, f8 = f4*f4;
        float denom = 3.0f - 1.00651f*f2 - 0.962251f*f4 + 1.47353f*f6 - 0.48953f*f8;
        float p = 1.0f - 2.0f*(1.0f - f)*(1.0f + 1.01524f*f) * frcp(fmaxf(denom, EPS));
        float Z = 2.0f*f * frcp(fmaxf(1.0f - p, 1e-6f));
        Z = fminf(Z, 85.0f);
        float zsz;
        if (fabsf(Z) < 1e-4f) {
            float z2 = Z*Z;
            zsz = 1.0f - z2*(1.0f/6.0f) + z2*z2*(1.0f/120.0f);
        } else {
            float E  = fex2(Z * LOG2E);
            float Em = fex2(-Z * LOG2E);
            zsz = Z * frcp(0.5f * (E - Em));
        }
        float A = N * INV4PI * zsz;              // A > 0
        La[s] = flg2(A);
        float scl = Z * LOG2E * rs;
        Kx[s] = Fx[s]*scl; Ky[s] = Fy[s]*scl; Kz[s] = Fz[s]*scl;
    }

    // acc[4s+k]: totals of (w*g_s)*{1,dx,dy,dz};
    // acc[16+k]: sum over {delta>=0} of w*u*{...}; acc[20+k]: same for w*v
    float acc[24];
    #pragma unroll
    for (int i = 0; i < 24; i++) acc[i] = 0.0f;

    if (paired) {
        #pragma unroll 5
        for (int pr = hl; pr < 400; pr += 16) {
            float4 q = s_dir[pr];                // broadcast across half-warps
            float lw = q.w;
            float gp[4], gm[4];
            #pragma unroll
            for (int s = 0; s < 4; s++) {
                float t = fmaf(Kx[s], q.x, fmaf(Ky[s], q.y, Kz[s]*q.z));
                float c = La[s] + lw;            // fold weight into exponent
                gp[s] = fex2(c + t);             // w*g at +d
                gm[s] = fex2(c - t);             // w*g at -d
                float sm = gp[s] + gm[s];
                float df = gp[s] - gm[s];
                acc[4*s+0] += sm;
                acc[4*s+1] = fmaf(df, q.x, acc[4*s+1]);
                acc[4*s+2] = fmaf(df, q.y, acc[4*s+2]);
                acc[4*s+3] = fmaf(df, q.z, acc[4*s+3]);
            }
            // branchless positive-delta buckets, +d member
            {
                float u = gp[0] - gp[2], v = gp[1] - gp[3];
                bool c1 = (u >= v);
                float uu = c1 ? u : 0.0f;
                float vv = c1 ? v : 0.0f;
                acc[16] += uu; acc[17] = fmaf(uu, q.x, acc[17]); acc[18] = fmaf(uu, q.y, acc[18]); acc[19] = fmaf(uu, q.z, acc[19]);
                acc[20] += vv; acc[21] = fmaf(vv, q.x, acc[21]); acc[22] = fmaf(vv, q.y, acc[22]); acc[23] = fmaf(vv, q.z, acc[23]);
            }
            // -d member (moments with negated direction)
            {
                float u = gm[0] - gm[2], v = gm[1] - gm[3];
                bool c2 = (u >= v);
                float uu = c2 ? u : 0.0f;
                float vv = c2 ? v : 0.0f;
                acc[16] += uu; acc[17] = fmaf(uu, -q.x, acc[17]); acc[18] = fmaf(uu, -q.y, acc[18]); acc[19] = fmaf(uu, -q.z, acc[19]);
                acc[20] += vv; acc[21] = fmaf(vv, -q.x, acc[21]); acc[22] = fmaf(vv, -q.y, acc[22]); acc[23] = fmaf(vv, -q.z, acc[23]);
            }
        }
    } else {
        for (int d = hl; d < nd; d += 16) {
            float4 q = s_dir[d];
            float lw = q.w;
            float g[4];
            #pragma unroll
            for (int s = 0; s < 4; s++) {
                float t = fmaf(Kx[s], q.x, fmaf(Ky[s], q.y, Kz[s]*q.z));
                g[s] = fex2(t + La[s] + lw);
                acc[4*s+0] += g[s];
                acc[4*s+1] = fmaf(g[s], q.x, acc[4*s+1]);
                acc[4*s+2] = fmaf(g[s], q.y, acc[4*s+2]);
                acc[4*s+3] = fmaf(g[s], q.z, acc[4*s+3]);
            }
            float wu = g[0] - g[2], wv = g[1] - g[3];
            bool c1 = (wu >= wv);
            float uu = c1 ? wu : 0.0f;
            float vv = c1 ? wv : 0.0f;
            acc[16] += uu; acc[17] = fmaf(uu, q.x, acc[17]); acc[18] = fmaf(uu, q.y, acc[18]); acc[19] = fmaf(uu, q.z, acc[19]);
            acc[20] += vv; acc[21] = fmaf(vv, q.x, acc[21]); acc[22] = fmaf(vv, q.y, acc[22]); acc[23] = fmaf(vv, q.z, acc[23]);
        }
    }

    // 16-wide butterfly reduction (stays within each half-warp);
    // afterwards every lane holds its batch's 24 totals
    #pragma unroll
    for (int off = 8; off > 0; off >>= 1) {
        #pragma unroll
        for (int i = 0; i < 24; i++)
            acc[i] += __shfl_xor_sync(0xffffffffu, acc[i], off);
    }

    float Su[4], Sv[4];
    #pragma unroll
    for (int k = 0; k < 4; k++) {
        Su[k] = acc[0 + k] - acc[8 + k];   // total sum w*u*{1,x,y,z}
        Sv[k] = acc[4 + k] - acc[12 + k];  // total sum w*v*{1,x,y,z}
    }
    float Iplus  = acc[16] - acc[20];
    float Iminus = (Sv[0] - acc[20]) - (Su[0] - acc[16]);
    float Ips = fmaxf(Iplus,  EPS);
    float Ims = fmaxf(Iminus, EPS);
    float cp, cn;
    if (Iplus < Iminus) {
        cp = 1.0f / 3.0f;
        cn = fminf(fmaxf(1.0f - (2.0f/3.0f)*(Ips/Ims), 0.0f), 1.0f);
    } else {
        cn = 1.0f / 3.0f;
        cp = fminf(fmaxf(1.0f - (2.0f/3.0f)*(Ims/Ips), 0.0f), 1.0f);
    }
    float growth = sqrtf(fmaxf(Iplus * Iminus, 0.0f));

    float n0[4], n1[4], n2[4], n3[4];
    #pragma unroll
    for (int k = 0; k < 4; k++) {
        float Pu = cp*acc[16 + k] + cn*(Su[k] - acc[16 + k]);  // sum w*Psur*u
        float Pv = cp*acc[20 + k] + cn*(Sv[k] - acc[20 + k]);  // sum w*Psur*v
        n0[k] = acc[8 + k]  + Pu;                              // e
        n1[k] = acc[12 + k] + Pv;                              // ebar
        n2[k] = 0.5f*(acc[0 + k] + acc[8 + k])  - 0.5f*Pu;     // x
        n3[k] = 0.5f*(acc[4 + k] + acc[12 + k]) - 0.5f*Pv;     // xbar
    }

    // F4mix layout (B,2,3,4): channel order [Fx,Fy,Fz,N]
    if (active) {
        float4* ob = (float4*)(out + (size_t)b * 24);
        if (hl == 0) ob[0] = make_float4(n0[1], n0[2], n0[3], n0[0]); // i=0,f=0 (e)
        if (hl == 1) ob[1] = make_float4(n2[1], n2[2], n2[3], n2[0]); // i=0,f=1 (x)
        if (hl == 2) ob[2] = make_float4(n2[1], n2[2], n2[3], n2[0]); // i=0,f=2 (x)
        if (hl == 3) ob[3] = make_float4(n1[1], n1[2], n1[3], n1[0]); // i=1,f=0 (ebar)
        if (hl == 4) ob[4] = make_float4(n3[1], n3[2], n3[3], n3[0]); // i=1,f=1 (xbar)
        if (hl == 5) ob[5] = make_float4(n3[1], n3[2], n3[3], n3[0]); // i=1,f=2 (xbar)
        if (hl == 6) out[(size_t)B * 24 + b] = growth;
    }
}

extern "C" void kernel_launch(void* const* d_in, const int* in_sizes, int n_in,
                              void* d_out, int out_size) {
    const float* F4  = (const float*)d_in[0];
    const float* ddx = (const float*)d_in[1];
    const float* ddy = (const float*)d_in[2];
    const float* ddz = (const float*)d_in[3];
    const float* dqw = (const float*)d_in[4];
    float* out = (float*)d_out;

    int B  = in_sizes[0] / 24;
    int nd = in_sizes[1];

    const int batches_per_block = WARPS_PER_BLOCK * 2;
    int grid = (B + batches_per_block - 1) / batches_per_block;
    closure_kernel<<<grid, NTHREADS>>>(F4, ddx, ddy, ddz, dqw, out, B, nd);
}

// round 9
// speedup vs baseline: 2.0322x; 1.1196x over previous
#include <cuda_runtime.h>
#include <cuda_bf16.h>

#define WARPS_PER_BLOCK 8
#define NTHREADS (WARPS_PER_BLOCK * 32)
#define NDIR_MAX 800
#define BATCHES_PER_WARP 4

__device__ __forceinline__ float fex2(float x){ float r; asm("ex2.approx.f32 %0,%1;" : "=f"(r) : "f"(x)); return r; }
__device__ __forceinline__ float flg2(float x){ float r; asm("lg2.approx.f32 %0,%1;" : "=f"(r) : "f"(x)); return r; }
__device__ __forceinline__ float frcp(float x){ float r; asm("rcp.approx.f32 %0,%1;" : "=f"(r) : "f"(x)); return r; }

__global__ __launch_bounds__(NTHREADS, 4)
void closure_kernel(const float* __restrict__ F4,
                    const float* __restrict__ gdx,
                    const float* __restrict__ gdy,
                    const float* __restrict__ gdz,
                    const float* __restrict__ gqw,
                    float* __restrict__ out,
                    int B, int nd)
{
    // paired path: dirs 0..399 have exact antipodes 400..799 with equal weight
    __shared__ float4 s_dir[NDIR_MAX];               // (dx,dy,dz, log2(w))
    const bool paired = (nd == 800);
    const int ntab = paired ? 400 : nd;
    for (int j = threadIdx.x; j < ntab; j += NTHREADS)
        s_dir[j] = make_float4(gdx[j], gdy[j], gdz[j], flg2(gqw[j]));
    __syncthreads();

    const int warp = threadIdx.x >> 5;
    const int lane = threadIdx.x & 31;
    const int hl   = lane & 7;                       // lane within 8-lane group
    // four batches per warp: lanes [0-7]->b0, [8-15]->b1, [16-23]->b2, [24-31]->b3
    int b = blockIdx.x * (WARPS_PER_BLOCK * BATCHES_PER_WARP)
          + warp * BATCHES_PER_WARP + (lane >> 3);
    bool active = (b < B);
    int bs = active ? b : 0;                         // safe index for loads

    const float EPS    = 1e-12f;
    const float INV4PI = 0.07957747154594767f;
    const float LOG2E  = 1.4426950408889634f;

    // vectorized input load: 24 floats = 6 float4 (per-group batch)
    const float4* in4 = (const float4*)(F4 + (size_t)bs * 24);
    float4 i0 = in4[0], i1 = in4[1], i2 = in4[2], i3 = in4[3], i4 = in4[4], i5 = in4[5];

    // species: 0=e, 1=ebar, 2=x, 3=xbar
    float Fx[4], Fy[4], Fz[4], Ns[4];
    Fx[0] = i0.x;  Fy[0] = i0.y;  Fz[0] = i0.z;  Ns[0] = i0.w;
    Fx[1] = i3.x;  Fy[1] = i3.y;  Fz[1] = i3.z;  Ns[1] = i3.w;
    Fx[2] = 0.5f*(i1.x + i2.x); Fy[2] = 0.5f*(i1.y + i2.y);
    Fz[2] = 0.5f*(i1.z + i2.z); Ns[2] = 0.5f*(i1.w + i2.w);
    Fx[3] = 0.5f*(i4.x + i5.x); Fy[3] = 0.5f*(i4.y + i5.y);
    Fz[3] = 0.5f*(i4.z + i5.z); Ns[3] = 0.5f*(i4.w + i5.w);

    float La[4], Kx[4], Ky[4], Kz[4];
    #pragma unroll
    for (int s = 0; s < 4; s++) {
        float N   = fmaxf(Ns[s], EPS);
        float ss  = Fx[s]*Fx[s] + Fy[s]*Fy[s] + Fz[s]*Fz[s];
        float rs  = rsqrtf(fmaxf(ss, 1e-30f));   // 1/nrm
        float nrm = ss * rs;
        float f   = fminf(fmaxf(nrm * frcp(N), 0.0f), 0.999999f);
        float f2 = f*f, f4 = f2*f2, f6 = f4*f2, f8 = f4*f4;
        float denom = 3.0f - 1.00651f*f2 - 0.962251f*f4 + 1.47353f*f6 - 0.48953f*f8;
        float p = 1.0f - 2.0f*(1.0f - f)*(1.0f + 1.01524f*f) * frcp(fmaxf(denom, EPS));
        float Z = 2.0f*f * frcp(fmaxf(1.0f - p, 1e-6f));
        Z = fminf(Z, 85.0f);
        float zsz;
        if (fabsf(Z) < 1e-4f) {
            float z2 = Z*Z;
            zsz = 1.0f - z2*(1.0f/6.0f) + z2*z2*(1.0f/120.0f);
        } else {
            float E  = fex2(Z * LOG2E);
            float Em = fex2(-Z * LOG2E);
            zsz = Z * frcp(0.5f * (E - Em));
        }
        float A = N * INV4PI * zsz;              // A > 0
        La[s] = flg2(A);
        float scl = Z * LOG2E * rs;
        Kx[s] = Fx[s]*scl; Ky[s] = Fy[s]*scl; Kz[s] = Fz[s]*scl;
    }

    // acc[4s+k]: totals of (w*g_s)*{1,dx,dy,dz};
    // acc[16+k]: sum over {delta>=0} of w*u*{...}; acc[20+k]: same for w*v
    float acc[24];
    #pragma unroll
    for (int i = 0; i < 24; i++) acc[i] = 0.0f;

    if (paired) {
        #pragma unroll 5
        for (int pr = hl; pr < 400; pr += 8) {
            float4 q = s_dir[pr];                // 8 distinct addrs, broadcast in groups
            float lw = q.w;
            float gp[4], gm[4];
            #pragma unroll
            for (int s = 0; s < 4; s++) {
                float t = fmaf(Kx[s], q.x, fmaf(Ky[s], q.y, Kz[s]*q.z));
                float c = La[s] + lw;            // fold weight into exponent
                gp[s] = fex2(c + t);             // w*g at +d
                gm[s] = fex2(c - t);             // w*g at -d
                float sm = gp[s] + gm[s];
                float df = gp[s] - gm[s];
                acc[4*s+0] += sm;
                acc[4*s+1] = fmaf(df, q.x, acc[4*s+1]);
                acc[4*s+2] = fmaf(df, q.y, acc[4*s+2]);
                acc[4*s+3] = fmaf(df, q.z, acc[4*s+3]);
            }
            // branchless positive-delta buckets, +d member
            {
                float u = gp[0] - gp[2], v = gp[1] - gp[3];
                bool c1 = (u >= v);
                float uu = c1 ? u : 0.0f;
                float vv = c1 ? v : 0.0f;
                acc[16] += uu; acc[17] = fmaf(uu, q.x, acc[17]); acc[18] = fmaf(uu, q.y, acc[18]); acc[19] = fmaf(uu, q.z, acc[19]);
                acc[20] += vv; acc[21] = fmaf(vv, q.x, acc[21]); acc[22] = fmaf(vv, q.y, acc[22]); acc[23] = fmaf(vv, q.z, acc[23]);
            }
            // -d member (moments with negated direction)
            {
                float u = gm[0] - gm[2], v = gm[1] - gm[3];
                bool c2 = (u >= v);
                float uu = c2 ? u : 0.0f;
                float vv = c2 ? v : 0.0f;
                acc[16] += uu; acc[17] = fmaf(uu, -q.x, acc[17]); acc[18] = fmaf(uu, -q.y, acc[18]); acc[19] = fmaf(uu, -q.z, acc[19]);
                acc[20] += vv; acc[21] = fmaf(vv, -q.x, acc[21]); acc[22] = fmaf(vv, -q.y, acc[22]); acc[23] = fmaf(vv, -q.z, acc[23]);
            }
        }
    } else {
        for (int d = hl; d < nd; d += 8) {
            float4 q = s_dir[d];
            float lw = q.w;
            float g[4];
            #pragma unroll
            for (int s = 0; s < 4; s++) {
                float t = fmaf(Kx[s], q.x, fmaf(Ky[s], q.y, Kz[s]*q.z));
                g[s] = fex2(t + La[s] + lw);
                acc[4*s+0] += g[s];
                acc[4*s+1] = fmaf(g[s], q.x, acc[4*s+1]);
                acc[4*s+2] = fmaf(g[s], q.y, acc[4*s+2]);
                acc[4*s+3] = fmaf(g[s], q.z, acc[4*s+3]);
            }
            float wu = g[0] - g[2], wv = g[1] - g[3];
            bool c1 = (wu >= wv);
            float uu = c1 ? wu : 0.0f;
            float vv = c1 ? wv : 0.0f;
            acc[16] += uu; acc[17] = fmaf(uu, q.x, acc[17]); acc[18] = fmaf(uu, q.y, acc[18]); acc[19] = fmaf(uu, q.z, acc[19]);
            acc[20] += vv; acc[21] = fmaf(vv, q.x, acc[21]); acc[22] = fmaf(vv, q.y, acc[22]); acc[23] = fmaf(vv, q.z, acc[23]);
        }
    }

    // 8-wide butterfly reduction (stays within each 8-lane group);
    // afterwards every lane holds its batch's 24 totals
    #pragma unroll
    for (int off = 4; off > 0; off >>= 1) {
        #pragma unroll
        for (int i = 0; i < 24; i++)
            acc[i] += __shfl_xor_sync(0xffffffffu, acc[i], off);
    }

    float Su[4], Sv[4];
    #pragma unroll
    for (int k = 0; k < 4; k++) {
        Su[k] = acc[0 + k] - acc[8 + k];   // total sum w*u*{1,x,y,z}
        Sv[k] = acc[4 + k] - acc[12 + k];  // total sum w*v*{1,x,y,z}
    }
    float Iplus  = acc[16] - acc[20];
    float Iminus = (Sv[0] - acc[20]) - (Su[0] - acc[16]);
    float Ips = fmaxf(Iplus,  EPS);
    float Ims = fmaxf(Iminus, EPS);
    float cp, cn;
    if (Iplus < Iminus) {
        cp = 1.0f / 3.0f;
        cn = fminf(fmaxf(1.0f - (2.0f/3.0f)*(Ips/Ims), 0.0f), 1.0f);
    } else {
        cn = 1.0f / 3.0f;
        cp = fminf(fmaxf(1.0f - (2.0f/3.0f)*(Ims/Ips), 0.0f), 1.0f);
    }
    float growth = sqrtf(fmaxf(Iplus * Iminus, 0.0f));

    float n0[4], n1[4], n2[4], n3[4];
    #pragma unroll
    for (int k = 0; k < 4; k++) {
        float Pu = cp*acc[16 + k] + cn*(Su[k] - acc[16 + k]);  // sum w*Psur*u
        float Pv = cp*acc[20 + k] + cn*(Sv[k] - acc[20 + k]);  // sum w*Psur*v
        n0[k] = acc[8 + k]  + Pu;                              // e
        n1[k] = acc[12 + k] + Pv;                              // ebar
        n2[k] = 0.5f*(acc[0 + k] + acc[8 + k])  - 0.5f*Pu;     // x
        n3[k] = 0.5f*(acc[4 + k] + acc[12 + k]) - 0.5f*Pv;     // xbar
    }

    // F4mix layout (B,2,3,4): channel order [Fx,Fy,Fz,N]
    if (active) {
        float4* ob = (float4*)(out + (size_t)b * 24);
        if (hl == 0) ob[0] = make_float4(n0[1], n0[2], n0[3], n0[0]); // i=0,f=0 (e)
        if (hl == 1) ob[1] = make_float4(n2[1], n2[2], n2[3], n2[0]); // i=0,f=1 (x)
        if (hl == 2) ob[2] = make_float4(n2[1], n2[2], n2[3], n2[0]); // i=0,f=2 (x)
        if (hl == 3) ob[3] = make_float4(n1[1], n1[2], n1[3], n1[0]); // i=1,f=0 (ebar)
        if (hl == 4) ob[4] = make_float4(n3[1], n3[2], n3[3], n3[0]); // i=1,f=1 (xbar)
        if (hl == 5) ob[5] = make_float4(n3[1], n3[2], n3[3], n3[0]); // i=1,f=2 (xbar)
        if (hl == 6) out[(size_t)B * 24 + b] = growth;
    }
}

extern "C" void kernel_launch(void* const* d_in, const int* in_sizes, int n_in,
                              void* d_out, int out_size) {
    const float* F4  = (const float*)d_in[0];
    const float* ddx = (const float*)d_in[1];
    const float* ddy = (const float*)d_in[2];
    const float* ddz = (const float*)d_in[3];
    const float* dqw = (const float*)d_in[4];
    float* out = (float*)d_out;

    int B  = in_sizes[0] / 24;
    int nd = in_sizes[1];

    const int batches_per_block = WARPS_PER_BLOCK * BATCHES_PER_WARP;
    int grid = (B + batches_per_block - 1) / batches_per_block;
    closure_kernel<<<grid, NTHREADS>>>(F4, ddx, ddy, ddz, dqw, out, B, nd);
}

// round 10
// speedup vs baseline: 2.1148x; 1.0406x over previous
#include <cuda_runtime.h>
#include <cuda_bf16.h>

#define WARPS_PER_BLOCK 4
#define NTHREADS (WARPS_PER_BLOCK * 32)
#define NDIR_MAX 800
#define BATCHES_PER_WARP 8

__device__ __forceinline__ float fex2(float x){ float r; asm("ex2.approx.f32 %0,%1;" : "=f"(r) : "f"(x)); return r; }
__device__ __forceinline__ float flg2(float x){ float r; asm("lg2.approx.f32 %0,%1;" : "=f"(r) : "f"(x)); return r; }
__device__ __forceinline__ float frcp(float x){ float r; asm("rcp.approx.f32 %0,%1;" : "=f"(r) : "f"(x)); return r; }

__global__ __launch_bounds__(NTHREADS, 8)
void closure_kernel(const float* __restrict__ F4,
                    const float* __restrict__ gdx,
                    const float* __restrict__ gdy,
                    const float* __restrict__ gdz,
                    const float* __restrict__ gqw,
                    float* __restrict__ out,
                    int B, int nd)
{
    // paired path: dirs 0..399 have exact antipodes 400..799 with equal weight
    __shared__ float4 s_dir[NDIR_MAX];               // (dx,dy,dz, log2(w))
    const bool paired = (nd == 800);
    const int ntab = paired ? 400 : nd;
    for (int j = threadIdx.x; j < ntab; j += NTHREADS)
        s_dir[j] = make_float4(gdx[j], gdy[j], gdz[j], flg2(gqw[j]));
    __syncthreads();

    const int warp = threadIdx.x >> 5;
    const int lane = threadIdx.x & 31;
    const int hl   = lane & 3;                       // lane within 4-lane group
    // eight batches per warp: 4-lane groups
    int b = blockIdx.x * (WARPS_PER_BLOCK * BATCHES_PER_WARP)
          + warp * BATCHES_PER_WARP + (lane >> 2);
    bool active = (b < B);
    int bs = active ? b : 0;                         // safe index for loads

    const float EPS    = 1e-12f;
    const float INV4PI = 0.07957747154594767f;
    const float LOG2E  = 1.4426950408889634f;

    // vectorized input load: 24 floats = 6 float4 (per-group batch)
    const float4* in4 = (const float4*)(F4 + (size_t)bs * 24);
    float4 i0 = in4[0], i1 = in4[1], i2 = in4[2], i3 = in4[3], i4 = in4[4], i5 = in4[5];

    // species: 0=e, 1=ebar, 2=x, 3=xbar
    float Fx[4], Fy[4], Fz[4], Ns[4];
    Fx[0] = i0.x;  Fy[0] = i0.y;  Fz[0] = i0.z;  Ns[0] = i0.w;
    Fx[1] = i3.x;  Fy[1] = i3.y;  Fz[1] = i3.z;  Ns[1] = i3.w;
    Fx[2] = 0.5f*(i1.x + i2.x); Fy[2] = 0.5f*(i1.y + i2.y);
    Fz[2] = 0.5f*(i1.z + i2.z); Ns[2] = 0.5f*(i1.w + i2.w);
    Fx[3] = 0.5f*(i4.x + i5.x); Fy[3] = 0.5f*(i4.y + i5.y);
    Fz[3] = 0.5f*(i4.z + i5.z); Ns[3] = 0.5f*(i4.w + i5.w);

    float La[4], Kx[4], Ky[4], Kz[4];
    #pragma unroll
    for (int s = 0; s < 4; s++) {
        float N   = fmaxf(Ns[s], EPS);
        float ss  = Fx[s]*Fx[s] + Fy[s]*Fy[s] + Fz[s]*Fz[s];
        float rs  = rsqrtf(fmaxf(ss, 1e-30f));   // 1/nrm
        float nrm = ss * rs;
        float f   = fminf(fmaxf(nrm * frcp(N), 0.0f), 0.999999f);
        float f2 = f*f, f4 = f2*f2, f6 = f4*f2, f8 = f4*f4;
        float denom = 3.0f - 1.00651f*f2 - 0.962251f*f4 + 1.47353f*f6 - 0.48953f*f8;
        float p = 1.0f - 2.0f*(1.0f - f)*(1.0f + 1.01524f*f) * frcp(fmaxf(denom, EPS));
        float Z = 2.0f*f * frcp(fmaxf(1.0f - p, 1e-6f));
        Z = fminf(Z, 85.0f);
        float zsz;
        if (fabsf(Z) < 1e-4f) {
            float z2 = Z*Z;
            zsz = 1.0f - z2*(1.0f/6.0f) + z2*z2*(1.0f/120.0f);
        } else {
            float E  = fex2(Z * LOG2E);
            float Em = fex2(-Z * LOG2E);
            zsz = Z * frcp(0.5f * (E - Em));
        }
        float A = N * INV4PI * zsz;              // A > 0
        La[s] = flg2(A);
        float scl = Z * LOG2E * rs;
        Kx[s] = Fx[s]*scl; Ky[s] = Fy[s]*scl; Kz[s] = Fz[s]*scl;
    }

    // acc[4s+k]: totals of (w*g_s)*{1,dx,dy,dz};
    // acc[16+k]: sum over {delta>=0} of w*u*{...}; acc[20+k]: same for w*v
    float acc[24];
    #pragma unroll
    for (int i = 0; i < 24; i++) acc[i] = 0.0f;

    if (paired) {
        #pragma unroll 5
        for (int pr = hl; pr < 400; pr += 4) {
            float4 q = s_dir[pr];                // 4 distinct addrs/warp, broadcast
            float lw = q.w;
            float gp[4], gm[4];
            #pragma unroll
            for (int s = 0; s < 4; s++) {
                float t = fmaf(Kx[s], q.x, fmaf(Ky[s], q.y, Kz[s]*q.z));
                float c = La[s] + lw;            // fold weight into exponent
                gp[s] = fex2(c + t);             // w*g at +d
                gm[s] = fex2(c - t);             // w*g at -d
                float sm = gp[s] + gm[s];
                float df = gp[s] - gm[s];
                acc[4*s+0] += sm;
                acc[4*s+1] = fmaf(df, q.x, acc[4*s+1]);
                acc[4*s+2] = fmaf(df, q.y, acc[4*s+2]);
                acc[4*s+3] = fmaf(df, q.z, acc[4*s+3]);
            }
            // branchless positive-delta buckets, +d member
            {
                float u = gp[0] - gp[2], v = gp[1] - gp[3];
                bool c1 = (u >= v);
                float uu = c1 ? u : 0.0f;
                float vv = c1 ? v : 0.0f;
                acc[16] += uu; acc[17] = fmaf(uu, q.x, acc[17]); acc[18] = fmaf(uu, q.y, acc[18]); acc[19] = fmaf(uu, q.z, acc[19]);
                acc[20] += vv; acc[21] = fmaf(vv, q.x, acc[21]); acc[22] = fmaf(vv, q.y, acc[22]); acc[23] = fmaf(vv, q.z, acc[23]);
            }
            // -d member (moments with negated direction)
            {
                float u = gm[0] - gm[2], v = gm[1] - gm[3];
                bool c2 = (u >= v);
                float uu = c2 ? u : 0.0f;
                float vv = c2 ? v : 0.0f;
                acc[16] += uu; acc[17] = fmaf(uu, -q.x, acc[17]); acc[18] = fmaf(uu, -q.y, acc[18]); acc[19] = fmaf(uu, -q.z, acc[19]);
                acc[20] += vv; acc[21] = fmaf(vv, -q.x, acc[21]); acc[22] = fmaf(vv, -q.y, acc[22]); acc[23] = fmaf(vv, -q.z, acc[23]);
            }
        }
    } else {
        for (int d = hl; d < nd; d += 4) {
            float4 q = s_dir[d];
            float lw = q.w;
            float g[4];
            #pragma unroll
            for (int s = 0; s < 4; s++) {
                float t = fmaf(Kx[s], q.x, fmaf(Ky[s], q.y, Kz[s]*q.z));
                g[s] = fex2(t + La[s] + lw);
                acc[4*s+0] += g[s];
                acc[4*s+1] = fmaf(g[s], q.x, acc[4*s+1]);
                acc[4*s+2] = fmaf(g[s], q.y, acc[4*s+2]);
                acc[4*s+3] = fmaf(g[s], q.z, acc[4*s+3]);
            }
            float wu = g[0] - g[2], wv = g[1] - g[3];
            bool c1 = (wu >= wv);
            float uu = c1 ? wu : 0.0f;
            float vv = c1 ? wv : 0.0f;
            acc[16] += uu; acc[17] = fmaf(uu, q.x, acc[17]); acc[18] = fmaf(uu, q.y, acc[18]); acc[19] = fmaf(uu, q.z, acc[19]);
            acc[20] += vv; acc[21] = fmaf(vv, q.x, acc[21]); acc[22] = fmaf(vv, q.y, acc[22]); acc[23] = fmaf(vv, q.z, acc[23]);
        }
    }

    // 4-wide butterfly reduction (stays within each 4-lane group);
    // afterwards every lane holds its batch's 24 totals
    #pragma unroll
    for (int off = 2; off > 0; off >>= 1) {
        #pragma unroll
        for (int i = 0; i < 24; i++)
            acc[i] += __shfl_xor_sync(0xffffffffu, acc[i], off);
    }

    float Su[4], Sv[4];
    #pragma unroll
    for (int k = 0; k < 4; k++) {
        Su[k] = acc[0 + k] - acc[8 + k];   // total sum w*u*{1,x,y,z}
        Sv[k] = acc[4 + k] - acc[12 + k];  // total sum w*v*{1,x,y,z}
    }
    float Iplus  = acc[16] - acc[20];
    float Iminus = (Sv[0] - acc[20]) - (Su[0] - acc[16]);
    float Ips = fmaxf(Iplus,  EPS);
    float Ims = fmaxf(Iminus, EPS);
    float cp, cn;
    if (Iplus < Iminus) {
        cp = 1.0f / 3.0f;
        cn = fminf(fmaxf(1.0f - (2.0f/3.0f)*(Ips/Ims), 0.0f), 1.0f);
    } else {
        cn = 1.0f / 3.0f;
        cp = fminf(fmaxf(1.0f - (2.0f/3.0f)*(Ims/Ips), 0.0f), 1.0f);
    }
    float growth = sqrtf(fmaxf(Iplus * Iminus, 0.0f));

    float n0[4], n1[4], n2[4], n3[4];
    #pragma unroll
    for (int k = 0; k < 4; k++) {
        float Pu = cp*acc[16 + k] + cn*(Su[k] - acc[16 + k]);  // sum w*Psur*u
        float Pv = cp*acc[20 + k] + cn*(Sv[k] - acc[20 + k]);  // sum w*Psur*v
        n0[k] = acc[8 + k]  + Pu;                              // e
        n1[k] = acc[12 + k] + Pv;                              // ebar
        n2[k] = 0.5f*(acc[0 + k] + acc[8 + k])  - 0.5f*Pu;     // x
        n3[k] = 0.5f*(acc[4 + k] + acc[12 + k]) - 0.5f*Pv;     // xbar
    }

    // F4mix layout (B,2,3,4): channel order [Fx,Fy,Fz,N]
    if (active) {
        float4* ob = (float4*)(out + (size_t)b * 24);
        if (hl == 0) { ob[0] = make_float4(n0[1], n0[2], n0[3], n0[0]);   // i=0,f=0 (e)
                       ob[4] = make_float4(n3[1], n3[2], n3[3], n3[0]); } // i=1,f=1 (xbar)
        if (hl == 1) { ob[1] = make_float4(n2[1], n2[2], n2[3], n2[0]);   // i=0,f=1 (x)
                       ob[5] = make_float4(n3[1], n3[2], n3[3], n3[0]); } // i=1,f=2 (xbar)
        if (hl == 2) { ob[2] = make_float4(n2[1], n2[2], n2[3], n2[0]);   // i=0,f=2 (x)
                       out[(size_t)B * 24 + b] = growth; }
        if (hl == 3)   ob[3] = make_float4(n1[1], n1[2], n1[3], n1[0]);   // i=1,f=0 (ebar)
    }
}

extern "C" void kernel_launch(void* const* d_in, const int* in_sizes, int n_in,
                              void* d_out, int out_size) {
    const float* F4  = (const float*)d_in[0];
    const float* ddx = (const float*)d_in[1];
    const float* ddy = (const float*)d_in[2];
    const float* ddz = (const float*)d_in[3];
    const float* dqw = (const float*)d_in[4];
    float* out = (float*)d_out;

    int B  = in_sizes[0] / 24;
    int nd = in_sizes[1];

    const int batches_per_block = WARPS_PER_BLOCK * BATCHES_PER_WARP;
    int grid = (B + batches_per_block - 1) / batches_per_block;
    closure_kernel<<<grid, NTHREADS>>>(F4, ddx, ddy, ddz, dqw, out, B, nd);
}